// round 5
// baseline (speedup 1.0000x reference)
#include <cuda_runtime.h>
#include <cuda_fp16.h>
#include <cuda_fp8.h>
#include <math.h>
#include <stdint.h>

#define NS 305
#define SP 320
#define SPSP (SP * SP)
#define NB 64
#define NT 4096
#define NTAU 1023            // 4-gram steps (t=1..4092)
#define NSTEP (NTAU + 2)     // + Q-step + A-step
#define LOG_SCALE_D 8.317766166719343   // log(4096)
#define DITH1 1.0471f        // dither factor for copy 1 (compensated exactly via g_rs)

// ---------------- device globals (zero-initialized) ----------------
__device__ float g_I[SP];
__device__ __align__(16) float g_BmT[4][SP];              // BmT[a][s] = Bm[s][a]
__device__ __align__(16) float g_A32[SPSP];
__device__ __align__(16) float g_Q32[4][SPSP];
__device__ __align__(16) float g_R32[64 * SPSP];          // fp32 R_{abc}
__device__ __align__(16) unsigned char g_S[2 * 69 * SPSP]; // e5m2, 2 dither copies: 64 R, 4 Q, 1 A
__device__ __align__(16) float g_rs[2 * 69 * SP];         // alpha row multiplier 4096/q per copy
__device__ unsigned char g_gram[NB * NTAU];
__device__ unsigned char g_o0[NB];
__device__ unsigned char g_tail[NB];

__device__ __forceinline__ float warpSum(float x) {
    #pragma unroll
    for (int o = 16; o; o >>= 1) x += __shfl_down_sync(0xffffffffu, x, o);
    return x;
}
__device__ __forceinline__ float warpMax(float x) {
    #pragma unroll
    for (int o = 16; o; o >>= 1) x = fmaxf(x, __shfl_down_sync(0xffffffffu, x, o));
    return x;
}
__device__ __forceinline__ float warpMaxAll(float x) {   // butterfly: all lanes get max
    #pragma unroll
    for (int o = 16; o; o >>= 1) x = fmaxf(x, __shfl_xor_sync(0xffffffffu, x, o));
    return x;
}

__device__ __forceinline__ __half2 u2h(uint32_t u) { return *reinterpret_cast<__half2*>(&u); }
__device__ __forceinline__ uint32_t h2u(__half2 h) { return *reinterpret_cast<uint32_t*>(&h); }

#define BAR_SYNC(id, n)   asm volatile("bar.sync %0, %1;"   :: "n"(id), "n"(n) : "memory")
#define BAR_ARRIVE(id, n) asm volatile("bar.arrive %0, %1;" :: "n"(id), "n"(n) : "memory")

// ---------------- setup: I softmax + emission softmax ----------------
__global__ void k_setup(const float* __restrict__ initk, const float* __restrict__ emisk) {
    __shared__ float red[16];
    __shared__ float bval;
    int tid = threadIdx.x, wid = tid >> 5, lane = tid & 31;
    const int nw = 16;
    float v = (tid < NS) ? initk[tid] : -1e30f;
    float m = warpMax(v);
    if (lane == 0) red[wid] = m;
    __syncthreads();
    if (tid == 0) { float mm = -1e30f; for (int w = 0; w < nw; w++) mm = fmaxf(mm, red[w]); bval = mm; }
    __syncthreads();
    m = bval;
    float e = (tid < NS) ? expf(v - m) : 0.f;
    float s = warpSum(e);
    __syncthreads();
    if (lane == 0) red[wid] = s;
    __syncthreads();
    if (tid == 0) { float ss = 0.f; for (int w = 0; w < nw; w++) ss += red[w]; bval = ss; }
    __syncthreads();
    if (tid < NS) g_I[tid] = e / bval;

    if (tid < NS) {
        float x0 = emisk[tid * 4 + 0], x1 = emisk[tid * 4 + 1];
        float x2 = emisk[tid * 4 + 2], x3 = emisk[tid * 4 + 3];
        float mm = fmaxf(fmaxf(x0, x1), fmaxf(x2, x3));
        float e0 = expf(x0 - mm), e1 = expf(x1 - mm), e2 = expf(x2 - mm), e3 = expf(x3 - mm);
        float inv = 1.f / (e0 + e1 + e2 + e3);
        g_BmT[0][tid] = e0 * inv; g_BmT[1][tid] = e1 * inv;
        g_BmT[2][tid] = e2 * inv; g_BmT[3][tid] = e3 * inv;
    }
}

// ---------------- softmax rows of transition -> A32 ----------------
__global__ void k_softA(const float* __restrict__ trans) {
    __shared__ float red[10];
    __shared__ float bval;
    int r = blockIdx.x, tid = threadIdx.x;
    int wid = tid >> 5, lane = tid & 31;
    float v = (tid < NS) ? trans[r * NS + tid] : -1e30f;
    float m = warpMax(v);
    if (lane == 0) red[wid] = m;
    __syncthreads();
    if (tid == 0) { float mm = -1e30f; for (int w = 0; w < 10; w++) mm = fmaxf(mm, red[w]); bval = mm; }
    __syncthreads();
    m = bval;
    float e = (tid < NS) ? expf(v - m) : 0.f;
    float s = warpSum(e);
    __syncthreads();
    if (lane == 0) red[wid] = s;
    __syncthreads();
    if (tid == 0) { float ss = 0.f; for (int w = 0; w < 10; w++) ss += red[w]; bval = ss; }
    __syncthreads();
    if (tid < NS) g_A32[r * SP + tid] = e / bval;
}

// ---------------- observation -> gram indices ----------------
__global__ void k_gram(const float* __restrict__ inputs) {
    int b = blockIdx.x;
    const float* inb = inputs + (size_t)b * NT * 4;
    for (int tau = threadIdx.x; tau < NTAU; tau += blockDim.x) {
        int t0 = 1 + 4 * tau;
        unsigned g = 0;
        #pragma unroll
        for (int k = 0; k < 4; k++) {
            const float* p = inb + (size_t)(t0 + k) * 4;
            float fi = p[1] + 2.f * p[2] + 3.f * p[3];
            g = (g << 2) | (unsigned)(fi + 0.5f);
        }
        g_gram[b * NTAU + tau] = (unsigned char)g;
    }
    if (threadIdx.x == 0) {
        const float* p = inb;
        g_o0[b] = (unsigned char)(p[1] + 2.f * p[2] + 3.f * p[3] + 0.5f);
        unsigned tg = 0;
        #pragma unroll
        for (int k = 0; k < 3; k++) {
            const float* q = inb + (size_t)(4093 + k) * 4;
            tg = (tg << 2) | (unsigned)(q[1] + 2.f * q[2] + 3.f * q[3] + 0.5f);
        }
        g_tail[b] = (unsigned char)tg;
    }
}

// ---------------- fp32 GEMM with k-dim column scaling ----------------
// mode 0: Q_z = (A*D_z) @ A ; mode 1: R_z = (Q_a*D_b) @ Q_c
__global__ void __launch_bounds__(256) k_gemm(int mode) {
    int z = blockIdx.z;
    const float *Lp, *Rp, *sc;
    float* outf;
    if (mode == 0) {
        Lp = g_A32; Rp = g_A32; sc = g_BmT[z]; outf = g_Q32[z];
    } else {
        int a = z >> 4, bb = (z >> 2) & 3, c = z & 3;
        Lp = g_Q32[a]; sc = g_BmT[bb]; Rp = g_Q32[c]; outf = g_R32 + (size_t)z * SPSP;
    }
    int m0 = blockIdx.y * 64, n0 = blockIdx.x * 64;
    __shared__ __align__(16) float Ls[16][64];
    __shared__ __align__(16) float Rs[16][64];
    int tid = threadIdx.x;
    int tx = tid & 15, ty = tid >> 4;
    int lrow = tid >> 2, lk = (tid & 3) * 4;
    int rk = tid >> 4, rn = (tid & 15) * 4;

    float acc[4][4] = {};
    for (int k0 = 0; k0 < SP; k0 += 16) {
        float4 lv = *(const float4*)&Lp[(size_t)(m0 + lrow) * SP + k0 + lk];
        Ls[lk + 0][lrow] = lv.x * sc[k0 + lk + 0];
        Ls[lk + 1][lrow] = lv.y * sc[k0 + lk + 1];
        Ls[lk + 2][lrow] = lv.z * sc[k0 + lk + 2];
        Ls[lk + 3][lrow] = lv.w * sc[k0 + lk + 3];
        *(float4*)&Rs[rk][rn] = *(const float4*)&Rp[(size_t)(k0 + rk) * SP + n0 + rn];
        __syncthreads();
        #pragma unroll
        for (int kk = 0; kk < 16; kk++) {
            float4 av = *(const float4*)&Ls[kk][ty * 4];
            float4 bv = *(const float4*)&Rs[kk][tx * 4];
            acc[0][0] = fmaf(av.x, bv.x, acc[0][0]); acc[0][1] = fmaf(av.x, bv.y, acc[0][1]);
            acc[0][2] = fmaf(av.x, bv.z, acc[0][2]); acc[0][3] = fmaf(av.x, bv.w, acc[0][3]);
            acc[1][0] = fmaf(av.y, bv.x, acc[1][0]); acc[1][1] = fmaf(av.y, bv.y, acc[1][1]);
            acc[1][2] = fmaf(av.y, bv.z, acc[1][2]); acc[1][3] = fmaf(av.y, bv.w, acc[1][3]);
            acc[2][0] = fmaf(av.z, bv.x, acc[2][0]); acc[2][1] = fmaf(av.z, bv.y, acc[2][1]);
            acc[2][2] = fmaf(av.z, bv.z, acc[2][2]); acc[2][3] = fmaf(av.z, bv.w, acc[2][3]);
            acc[3][0] = fmaf(av.w, bv.x, acc[3][0]); acc[3][1] = fmaf(av.w, bv.y, acc[3][1]);
            acc[3][2] = fmaf(av.w, bv.z, acc[3][2]); acc[3][3] = fmaf(av.w, bv.w, acc[3][3]);
        }
        __syncthreads();
    }
    #pragma unroll
    for (int i = 0; i < 4; i++)
        #pragma unroll
        for (int j = 0; j < 4; j++)
            outf[(size_t)(m0 + ty * 4 + i) * SP + (n0 + tx * 4 + j)] = acc[i][j];
}

// ---------------- quantize to e5m2, warp-per-row, 2 dithered copies ----------------
// grid (40, 69, 2), block 256 (8 warps; warp w handles row blockIdx.x*8+w)
__global__ void k_quant() {
    int z = blockIdx.y, c = blockIdx.z;
    int warp = threadIdx.x >> 5, lane = threadIdx.x & 31;
    int r = blockIdx.x * 8 + warp;
    const float* src;
    if (z < 64) src = g_R32 + (size_t)z * SPSP;
    else if (z < 68) src = g_Q32[z - 64];
    else src = g_A32;
    const float* row = src + (size_t)r * SP;

    float vv[10];
    float mx = 0.f;
    #pragma unroll
    for (int i = 0; i < 10; i++) { vv[i] = row[lane + 32 * i]; mx = fmaxf(mx, vv[i]); }
    mx = warpMaxAll(mx);
    float q = (mx > 0.f) ? 384.f / mx : 1.f;
    if (c == 1) q *= DITH1;
    unsigned char* dst = g_S + ((size_t)c * 69 + z) * SPSP + (size_t)r * SP;
    #pragma unroll
    for (int i = 0; i < 10; i++)
        dst[lane + 32 * i] = (unsigned char)__nv_cvt_float_to_fp8(vv[i] * q, __NV_SATFINITE, __NV_E5M2);
    if (lane == 0) g_rs[(c * 69 + z) * SP + r] = 4096.f / q;
}

// ---------------- chain: persistent CTA per batch, deferred-normalization pipeline ----------------
// 640 threads: cp=tid%20 -> cols [16cp..16cp+15]; iq=tid/20 -> rows iq+32k (k<10).
// e5m2 -> f16 via PRMT (byte<<8 is bit-exact). alpha kept UNNORMALIZED (missing si);
// si applied one step late in the reduce (f32). Totals/log run post-barrier, overlapped.
__global__ void __launch_bounds__(640, 1) k_chain(float* __restrict__ out) {
    int b = blockIdx.x, tid = threadIdx.x;
    __shared__ uint32_t part[32][160];
    __shared__ __half2 ah2[SP];
    __shared__ float redp[8];
    __shared__ unsigned char sg[NTAU + 1];
    int lane = tid & 31, wid = tid >> 5;
    int iq = tid / 20;
    int cp = tid % 20;

    for (int i = tid; i < NTAU; i += 640) sg[i] = g_gram[b * NTAU + i];
    unsigned tg = g_tail[b];
    int o0 = g_o0[b];
    __syncthreads();
    int z0 = sg[0] >> 2;

    // ---- prologue: alpha0 = normalize(I * Bm[:,o0]); fully normalized (si_prev = 1) ----
    double ll = 0.0;
    {
        __shared__ float pr[20];
        __shared__ float psinv;
        float v0p = (tid < SP) ? g_I[tid] * g_BmT[o0][tid] : 0.f;
        float wsum = warpSum(v0p);
        if (lane == 0) pr[wid] = wsum;
        __syncthreads();
        if (tid == 0) {
            float x = 0.f;
            #pragma unroll
            for (int w = 0; w < 20; w++) x += pr[w];
            psinv = 1.f / x;
            ll = (double)logf(x);
            redp[0] = 1.f; redp[1] = 0.f; redp[2] = 0.f; redp[3] = 0.f; redp[4] = 0.f;
        }
        __syncthreads();
        float* af = (float*)&part[0][0];
        if (tid < SP) af[tid] = v0p * psinv;
        __syncthreads();
        if (tid < 160) {
            float2 rsv = *(const float2*)&g_rs[z0 * SP + 2 * tid];   // step 0 = copy 0
            float a0 = af[2 * tid] * rsv.x, a1 = af[2 * tid + 1] * rsv.y;
            ah2[2 * tid]     = __floats2half2_rn(a0, a0);
            ah2[2 * tid + 1] = __floats2half2_rn(a1, a1);
        }
        __syncthreads();
    }

    // ---- preload matrix regs for step 0 (copy 0) ----
    uint4 mr[10];
    {
        const uint4* p = (const uint4*)(g_S + (size_t)z0 * SPSP) + tid;
        #pragma unroll
        for (int k = 0; k < 10; k++) mr[k] = __ldcg(p + k * 640);
    }

    for (int step = 0; step < NSTEP; ++step) {
        int d, zn;
        if (step < NTAU) d = sg[step] & 3;
        else if (step == NTAU) d = (tg >> 2) & 3;
        else d = tg & 3;
        if (step + 1 < NTAU) zn = sg[step + 1] >> 2;
        else if (step + 1 == NTAU) zn = 64 + ((tg >> 4) & 3);
        else zn = 68;
        int zoff = ((step + 1) & 1) * 69 + zn;     // dither copy alternates by step

        // ---- FMA phase (all 640 threads): PRMT expand + HFMA2, raw (un-si'd) alpha ----
        __half2 a0 = __floats2half2_rn(0.f, 0.f);
        __half2 a1 = a0, a2 = a0, a3 = a0, a4 = a0, a5 = a0, a6 = a0, a7 = a0;
        #pragma unroll
        for (int k = 0; k < 10; k++) {
            __half2 av = ah2[iq + 32 * k];
            a0 = __hfma2(av, u2h(__byte_perm(mr[k].x, 0, 0x1404)), a0);
            a1 = __hfma2(av, u2h(__byte_perm(mr[k].x, 0, 0x3424)), a1);
            a2 = __hfma2(av, u2h(__byte_perm(mr[k].y, 0, 0x1404)), a2);
            a3 = __hfma2(av, u2h(__byte_perm(mr[k].y, 0, 0x3424)), a3);
            a4 = __hfma2(av, u2h(__byte_perm(mr[k].z, 0, 0x1404)), a4);
            a5 = __hfma2(av, u2h(__byte_perm(mr[k].z, 0, 0x3424)), a5);
            a6 = __hfma2(av, u2h(__byte_perm(mr[k].w, 0, 0x1404)), a6);
            a7 = __hfma2(av, u2h(__byte_perm(mr[k].w, 0, 0x3424)), a7);
        }
        uint32_t* dst = &part[iq][cp * 8];
        *(uint4*)dst       = make_uint4(h2u(a0), h2u(a1), h2u(a2), h2u(a3));
        *(uint4*)(dst + 4) = make_uint4(h2u(a4), h2u(a5), h2u(a6), h2u(a7));

        float v0, v1, tot;
        if (tid < 160) {
            // prefetch next-step row scales + this-step fold (off critical path)
            float2 rsv = *(const float2*)&g_rs[zoff * SP + 2 * tid];
            float2 fo  = *(const float2*)&g_BmT[d][2 * tid];
            BAR_SYNC(1, 640);                       // all partials written
            // si from previous step's totals (redp ordered by bar chain)
            tot = redp[0] + redp[1] + redp[2] + redp[3] + redp[4];
            float si = __frcp_rn(tot);
            // dual-chain sum of 32 f16x2 partials
            __half2 sA = __floats2half2_rn(0.f, 0.f), sB = sA;
            #pragma unroll
            for (int k = 0; k < 32; k += 2) {
                sA = __hadd2(sA, *(const __half2*)&part[k][tid]);
                sB = __hadd2(sB, *(const __half2*)&part[k + 1][tid]);
            }
            float2 f2 = __half22float2(__hadd2(sA, sB));
            v0 = f2.x * fo.x * si;                  // corrected column values
            v1 = f2.y * fo.y * si;
            float b0 = v0 * rsv.x, b1 = v1 * rsv.y; // next alpha, UNNORMALIZED (si deferred)
            ah2[2 * tid]     = __floats2half2_rn(b0, b0);
            ah2[2 * tid + 1] = __floats2half2_rn(b1, b1);
            BAR_SYNC(2, 640);                       // alpha ready; full sync (no races)
            // ---- post-barrier window: overlapped with next FMA ----
            {   // next step's matrix loads
                const uint4* p = (const uint4*)(g_S + (size_t)zoff * SPSP) + tid;
                #pragma unroll
                for (int k = 0; k < 10; k++) mr[k] = __ldcg(p + k * 640);
            }
            float t = warpSum(v0 + v1);
            if (lane == 0) redp[wid] = t;           // this step's partial totals
            if (tid == 0) ll += log((double)tot);   // log of s_{step-1} (log(1)=0 at step 0)
        } else {
            BAR_ARRIVE(1, 640);                     // partials ready
            {   // next step's matrix loads (before waiting on alpha)
                const uint4* p = (const uint4*)(g_S + (size_t)zoff * SPSP) + tid;
                #pragma unroll
                for (int k = 0; k < 10; k++) mr[k] = __ldcg(p + k * 640);
            }
            BAR_SYNC(2, 640);                       // wait: alpha ready
        }
    }
    __syncthreads();
    if (tid == 0) {
        float tot = redp[0] + redp[1] + redp[2] + redp[3] + redp[4];  // s of last step
        ll += log((double)tot);
        out[b] = (float)(ll - (double)NSTEP * LOG_SCALE_D);
    }
}

// ---------------- launch ----------------
extern "C" void kernel_launch(void* const* d_in, const int* in_sizes, int n_in,
                              void* d_out, int out_size) {
    const float* inputs = (const float*)d_in[0];
    const float* initk  = (const float*)d_in[1];
    const float* transk = (const float*)d_in[2];
    const float* emisk  = (const float*)d_in[3];
    float* out = (float*)d_out;

    k_setup<<<1, 512>>>(initk, emisk);
    k_softA<<<NS, 320>>>(transk);
    k_gram<<<NB, 256>>>(inputs);
    k_gemm<<<dim3(5, 5, 4), 256>>>(0);
    k_gemm<<<dim3(5, 5, 64), 256>>>(1);
    k_quant<<<dim3(40, 69, 2), 256>>>();
    k_chain<<<NB, 640>>>(out);
}

// round 6
// speedup vs baseline: 1.2780x; 1.2780x over previous
#include <cuda_runtime.h>
#include <cuda_fp16.h>
#include <cuda_fp8.h>
#include <math.h>
#include <stdint.h>

#define NS 305
#define SP 320
#define SPSP (SP * SP)
#define NB 64
#define NT 4096
#define NTAU 1023            // 4-gram steps (t=1..4092)
#define NSTEP (NTAU + 2)     // + Q-step + A-step
#define LOG_SCALE_D 8.317766166719343   // log(4096)
#define DITH1 1.0471f        // dither factor for copy 1 (compensated exactly via g_rs)

// ---------------- device globals (zero-initialized) ----------------
__device__ float g_I[SP];
__device__ __align__(16) float g_BmT[4][SP];              // BmT[a][s] = Bm[s][a]
__device__ __align__(16) float g_A32[SPSP];
__device__ __align__(16) float g_Q32[4][SPSP];
__device__ __align__(16) float g_R32[64 * SPSP];          // fp32 R_{abc}
// e5m2, 2 dither copies, BLOCKED layout: byte for (row r, col c) at
// ((r>>5)*20 + (c>>4))*512 + (r&31)*16 + (c&15)
__device__ __align__(16) unsigned char g_S[2 * 69 * SPSP];
__device__ __align__(16) float g_rs[2 * 69 * SP];         // alpha row multiplier 4096/q per copy
__device__ unsigned char g_gram[NB * NTAU];
__device__ unsigned char g_o0[NB];
__device__ unsigned char g_tail[NB];

__device__ __forceinline__ float warpSum(float x) {
    #pragma unroll
    for (int o = 16; o; o >>= 1) x += __shfl_down_sync(0xffffffffu, x, o);
    return x;
}
__device__ __forceinline__ float warpMax(float x) {
    #pragma unroll
    for (int o = 16; o; o >>= 1) x = fmaxf(x, __shfl_down_sync(0xffffffffu, x, o));
    return x;
}
__device__ __forceinline__ float warpMaxAll(float x) {
    #pragma unroll
    for (int o = 16; o; o >>= 1) x = fmaxf(x, __shfl_xor_sync(0xffffffffu, x, o));
    return x;
}

__device__ __forceinline__ __half2 u2h(uint32_t u) { return *reinterpret_cast<__half2*>(&u); }
__device__ __forceinline__ uint32_t h2u(__half2 h) { return *reinterpret_cast<uint32_t*>(&h); }
__device__ __forceinline__ uint32_t hadd2u(uint32_t a, uint32_t b) {
    return h2u(__hadd2(u2h(a), u2h(b)));
}

#define BAR_SYNC(id, n)   asm volatile("bar.sync %0, %1;"   :: "n"(id), "n"(n) : "memory")

// ---------------- setup: I softmax + emission softmax ----------------
__global__ void k_setup(const float* __restrict__ initk, const float* __restrict__ emisk) {
    __shared__ float red[16];
    __shared__ float bval;
    int tid = threadIdx.x, wid = tid >> 5, lane = tid & 31;
    const int nw = 16;
    float v = (tid < NS) ? initk[tid] : -1e30f;
    float m = warpMax(v);
    if (lane == 0) red[wid] = m;
    __syncthreads();
    if (tid == 0) { float mm = -1e30f; for (int w = 0; w < nw; w++) mm = fmaxf(mm, red[w]); bval = mm; }
    __syncthreads();
    m = bval;
    float e = (tid < NS) ? expf(v - m) : 0.f;
    float s = warpSum(e);
    __syncthreads();
    if (lane == 0) red[wid] = s;
    __syncthreads();
    if (tid == 0) { float ss = 0.f; for (int w = 0; w < nw; w++) ss += red[w]; bval = ss; }
    __syncthreads();
    if (tid < NS) g_I[tid] = e / bval;

    if (tid < NS) {
        float x0 = emisk[tid * 4 + 0], x1 = emisk[tid * 4 + 1];
        float x2 = emisk[tid * 4 + 2], x3 = emisk[tid * 4 + 3];
        float mm = fmaxf(fmaxf(x0, x1), fmaxf(x2, x3));
        float e0 = expf(x0 - mm), e1 = expf(x1 - mm), e2 = expf(x2 - mm), e3 = expf(x3 - mm);
        float inv = 1.f / (e0 + e1 + e2 + e3);
        g_BmT[0][tid] = e0 * inv; g_BmT[1][tid] = e1 * inv;
        g_BmT[2][tid] = e2 * inv; g_BmT[3][tid] = e3 * inv;
    }
}

// ---------------- softmax rows of transition -> A32 ----------------
__global__ void k_softA(const float* __restrict__ trans) {
    __shared__ float red[10];
    __shared__ float bval;
    int r = blockIdx.x, tid = threadIdx.x;
    int wid = tid >> 5, lane = tid & 31;
    float v = (tid < NS) ? trans[r * NS + tid] : -1e30f;
    float m = warpMax(v);
    if (lane == 0) red[wid] = m;
    __syncthreads();
    if (tid == 0) { float mm = -1e30f; for (int w = 0; w < 10; w++) mm = fmaxf(mm, red[w]); bval = mm; }
    __syncthreads();
    m = bval;
    float e = (tid < NS) ? expf(v - m) : 0.f;
    float s = warpSum(e);
    __syncthreads();
    if (lane == 0) red[wid] = s;
    __syncthreads();
    if (tid == 0) { float ss = 0.f; for (int w = 0; w < 10; w++) ss += red[w]; bval = ss; }
    __syncthreads();
    if (tid < NS) g_A32[r * SP + tid] = e / bval;
}

// ---------------- observation -> gram indices ----------------
__global__ void k_gram(const float* __restrict__ inputs) {
    int b = blockIdx.x;
    const float* inb = inputs + (size_t)b * NT * 4;
    for (int tau = threadIdx.x; tau < NTAU; tau += blockDim.x) {
        int t0 = 1 + 4 * tau;
        unsigned g = 0;
        #pragma unroll
        for (int k = 0; k < 4; k++) {
            const float* p = inb + (size_t)(t0 + k) * 4;
            float fi = p[1] + 2.f * p[2] + 3.f * p[3];
            g = (g << 2) | (unsigned)(fi + 0.5f);
        }
        g_gram[b * NTAU + tau] = (unsigned char)g;
    }
    if (threadIdx.x == 0) {
        const float* p = inb;
        g_o0[b] = (unsigned char)(p[1] + 2.f * p[2] + 3.f * p[3] + 0.5f);
        unsigned tg = 0;
        #pragma unroll
        for (int k = 0; k < 3; k++) {
            const float* q = inb + (size_t)(4093 + k) * 4;
            tg = (tg << 2) | (unsigned)(q[1] + 2.f * q[2] + 3.f * q[3] + 0.5f);
        }
        g_tail[b] = (unsigned char)tg;
    }
}

// ---------------- fp32 GEMM with k-dim column scaling ----------------
__global__ void __launch_bounds__(256) k_gemm(int mode) {
    int z = blockIdx.z;
    const float *Lp, *Rp, *sc;
    float* outf;
    if (mode == 0) {
        Lp = g_A32; Rp = g_A32; sc = g_BmT[z]; outf = g_Q32[z];
    } else {
        int a = z >> 4, bb = (z >> 2) & 3, c = z & 3;
        Lp = g_Q32[a]; sc = g_BmT[bb]; Rp = g_Q32[c]; outf = g_R32 + (size_t)z * SPSP;
    }
    int m0 = blockIdx.y * 64, n0 = blockIdx.x * 64;
    __shared__ __align__(16) float Ls[16][64];
    __shared__ __align__(16) float Rs[16][64];
    int tid = threadIdx.x;
    int tx = tid & 15, ty = tid >> 4;
    int lrow = tid >> 2, lk = (tid & 3) * 4;
    int rk = tid >> 4, rn = (tid & 15) * 4;

    float acc[4][4] = {};
    for (int k0 = 0; k0 < SP; k0 += 16) {
        float4 lv = *(const float4*)&Lp[(size_t)(m0 + lrow) * SP + k0 + lk];
        Ls[lk + 0][lrow] = lv.x * sc[k0 + lk + 0];
        Ls[lk + 1][lrow] = lv.y * sc[k0 + lk + 1];
        Ls[lk + 2][lrow] = lv.z * sc[k0 + lk + 2];
        Ls[lk + 3][lrow] = lv.w * sc[k0 + lk + 3];
        *(float4*)&Rs[rk][rn] = *(const float4*)&Rp[(size_t)(k0 + rk) * SP + n0 + rn];
        __syncthreads();
        #pragma unroll
        for (int kk = 0; kk < 16; kk++) {
            float4 av = *(const float4*)&Ls[kk][ty * 4];
            float4 bv = *(const float4*)&Rs[kk][tx * 4];
            acc[0][0] = fmaf(av.x, bv.x, acc[0][0]); acc[0][1] = fmaf(av.x, bv.y, acc[0][1]);
            acc[0][2] = fmaf(av.x, bv.z, acc[0][2]); acc[0][3] = fmaf(av.x, bv.w, acc[0][3]);
            acc[1][0] = fmaf(av.y, bv.x, acc[1][0]); acc[1][1] = fmaf(av.y, bv.y, acc[1][1]);
            acc[1][2] = fmaf(av.y, bv.z, acc[1][2]); acc[1][3] = fmaf(av.y, bv.w, acc[1][3]);
            acc[2][0] = fmaf(av.z, bv.x, acc[2][0]); acc[2][1] = fmaf(av.z, bv.y, acc[2][1]);
            acc[2][2] = fmaf(av.z, bv.z, acc[2][2]); acc[2][3] = fmaf(av.z, bv.w, acc[2][3]);
            acc[3][0] = fmaf(av.w, bv.x, acc[3][0]); acc[3][1] = fmaf(av.w, bv.y, acc[3][1]);
            acc[3][2] = fmaf(av.w, bv.z, acc[3][2]); acc[3][3] = fmaf(av.w, bv.w, acc[3][3]);
        }
        __syncthreads();
    }
    #pragma unroll
    for (int i = 0; i < 4; i++)
        #pragma unroll
        for (int j = 0; j < 4; j++)
            outf[(size_t)(m0 + ty * 4 + i) * SP + (n0 + tx * 4 + j)] = acc[i][j];
}

// ---------------- quantize to e5m2, warp-per-row, blocked layout, 2 dithered copies ----------------
// grid (40, 69, 2), block 256 (8 warps; warp w handles row blockIdx.x*8+w)
__global__ void k_quant() {
    int z = blockIdx.y, c = blockIdx.z;
    int warp = threadIdx.x >> 5, lane = threadIdx.x & 31;
    int r = blockIdx.x * 8 + warp;
    const float* src;
    if (z < 64) src = g_R32 + (size_t)z * SPSP;
    else if (z < 68) src = g_Q32[z - 64];
    else src = g_A32;
    const float* row = src + (size_t)r * SP;

    float vv[10];
    float mx = 0.f;
    #pragma unroll
    for (int i = 0; i < 10; i++) { vv[i] = row[lane + 32 * i]; mx = fmaxf(mx, vv[i]); }
    mx = warpMaxAll(mx);
    float q = (mx > 0.f) ? 384.f / mx : 1.f;
    if (c == 1) q *= DITH1;
    unsigned char* dst = g_S + ((size_t)c * 69 + z) * SPSP;
    int rk = r >> 5, rL = r & 31;
    #pragma unroll
    for (int i = 0; i < 10; i++) {
        int col = lane + 32 * i;
        // blocked: ((rk*20 + (col>>4))*32 + rL)*16 + (col&15)
        dst[(((rk * 20 + (col >> 4)) * 32 + rL) << 4) + (col & 15)] =
            (unsigned char)__nv_cvt_float_to_fp8(vv[i] * q, __NV_SATFINITE, __NV_E5M2);
    }
    if (lane == 0) g_rs[(c * 69 + z) * SP + r] = 4096.f / q;
}

// ---------------- chain: persistent CTA per batch, warp-column matvec, shfl reduce ----------------
// 640 threads = 20 warps. Warp w owns cols [16w,16w+16); lane = row-class (rows lane+32k, k<10).
// Blocked layout => load address base + tid + 640k (identical to coalesced R4 pattern).
// e5m2 -> f16 via PRMT (byte<<8 bit-exact). In-warp reg-halving shuffle reduce (no part[] smem).
__global__ void __launch_bounds__(640, 1) k_chain(float* __restrict__ out) {
    int b = blockIdx.x, tid = threadIdx.x;
    __shared__ __align__(16) float2 colbuf[160];   // un-normalized folded col values (pairs)
    __shared__ __half2 ah2[SP];                    // alpha duplicated pairs
    __shared__ __align__(16) float redp[20];       // per-warp partial totals
    __shared__ unsigned char sg[NTAU + 1];
    int lane = tid & 31, w = tid >> 5;

    for (int i = tid; i < NTAU; i += 640) sg[i] = g_gram[b * NTAU + i];
    unsigned tg = g_tail[b];
    int o0 = g_o0[b];
    __syncthreads();
    int z0 = sg[0] >> 2;

    // ---- prologue: alpha0 = normalize(I * Bm[:,o0]) ----
    float llf = 0.f, lcomp = 0.f;
    {
        __shared__ float pr[20];
        __shared__ float psinv;
        float v0p = (tid < SP) ? g_I[tid] * g_BmT[o0][tid] : 0.f;
        float wsum = warpSum(v0p);
        if (lane == 0) pr[w] = wsum;
        __syncthreads();
        if (tid == 0) {
            float x = 0.f;
            #pragma unroll
            for (int q = 0; q < 20; q++) x += pr[q];
            psinv = 1.f / x;
            pr[0] = x;
        }
        __syncthreads();
        llf = logf(pr[0]);
        float* af = (float*)colbuf;
        if (tid < SP) af[tid] = v0p * psinv;
        __syncthreads();
        if (tid < 160) {
            float2 rsv = *(const float2*)&g_rs[z0 * SP + 2 * tid];   // step 0 = copy 0
            float a0 = af[2 * tid] * rsv.x, a1 = af[2 * tid + 1] * rsv.y;
            ah2[2 * tid]     = __floats2half2_rn(a0, a0);
            ah2[2 * tid + 1] = __floats2half2_rn(a1, a1);
        }
        __syncthreads();
    }

    // ---- preload matrix regs for step 0 (copy 0) ----
    uint4 mr[10];
    {
        const uint4* p = (const uint4*)(g_S + (size_t)z0 * SPSP) + tid;
        #pragma unroll
        for (int k = 0; k < 10; k++) mr[k] = __ldcg(p + k * 640);
    }

    int bit0 = lane & 1, bit1 = (lane >> 1) & 1, bit2 = (lane >> 2) & 1;
    int j8 = lane & 7;

    for (int step = 0; step < NSTEP; ++step) {
        int d, zn;
        if (step < NTAU) d = sg[step] & 3;
        else if (step == NTAU) d = (tg >> 2) & 3;
        else d = tg & 3;
        if (step + 1 < NTAU) zn = sg[step + 1] >> 2;
        else if (step + 1 == NTAU) zn = 64 + ((tg >> 4) & 3);
        else zn = 68;
        int zoff = ((step + 1) & 1) * 69 + zn;     // dither copy alternates by step

        // prefetch fold for this step's cols (lanes 0-7 use) + next row-scales (tid<160 use)
        float2 fo = *(const float2*)&g_BmT[d][16 * w + 2 * j8];
        float2 rsv = (tid < 160) ? *(const float2*)&g_rs[(size_t)zoff * SP + 2 * tid]
                                 : make_float2(0.f, 0.f);

        // ---- FMA phase: warp w, cols 16w..16w+15; lane rows lane+32k ----
        __half2 a0 = __floats2half2_rn(0.f, 0.f);
        __half2 a1 = a0, a2 = a0, a3 = a0, a4 = a0, a5 = a0, a6 = a0, a7 = a0;
        #pragma unroll
        for (int k = 0; k < 10; k++) {
            __half2 av = ah2[lane + 32 * k];
            a0 = __hfma2(av, u2h(__byte_perm(mr[k].x, 0, 0x1404)), a0);
            a1 = __hfma2(av, u2h(__byte_perm(mr[k].x, 0, 0x3424)), a1);
            a2 = __hfma2(av, u2h(__byte_perm(mr[k].y, 0, 0x1404)), a2);
            a3 = __hfma2(av, u2h(__byte_perm(mr[k].y, 0, 0x3424)), a3);
            a4 = __hfma2(av, u2h(__byte_perm(mr[k].z, 0, 0x1404)), a4);
            a5 = __hfma2(av, u2h(__byte_perm(mr[k].z, 0, 0x3424)), a5);
            a6 = __hfma2(av, u2h(__byte_perm(mr[k].w, 0, 0x1404)), a6);
            a7 = __hfma2(av, u2h(__byte_perm(mr[k].w, 0, 0x3424)), a7);
        }

        // ---- issue next step's matrix loads NOW (mr free; latency covered by reduce+B) ----
        {
            const uint4* p = (const uint4*)(g_S + (size_t)zoff * SPSP) + tid;
            #pragma unroll
            for (int k = 0; k < 10; k++) mr[k] = __ldcg(p + k * 640);
        }

        // ---- in-warp reg-halving reduce over 32 lanes ----
        // h[j] = col pair (16w+2j, 16w+2j+1). After rounds: lane holds pair j = lane&7.
        uint32_t h0 = h2u(a0), h1 = h2u(a1), h2v = h2u(a2), h3 = h2u(a3);
        uint32_t h4 = h2u(a4), h5 = h2u(a5), h6 = h2u(a6), h7 = h2u(a7);
        // round 1 (xor 1): keep j with bit0 == lane bit0
        {
            uint32_t g0 = bit0 ? h0 : h1, g1 = bit0 ? h2v : h3;
            uint32_t g2 = bit0 ? h4 : h5, g3 = bit0 ? h6 : h7;
            uint32_t r0 = __shfl_xor_sync(0xffffffffu, g0, 1);
            uint32_t r1 = __shfl_xor_sync(0xffffffffu, g1, 1);
            uint32_t r2 = __shfl_xor_sync(0xffffffffu, g2, 1);
            uint32_t r3 = __shfl_xor_sync(0xffffffffu, g3, 1);
            h0 = hadd2u(bit0 ? h1 : h0, r0);
            h1 = hadd2u(bit0 ? h3 : h2v, r1);
            h2v = hadd2u(bit0 ? h5 : h4, r2);
            h3 = hadd2u(bit0 ? h7 : h6, r3);
        }
        // round 2 (xor 2)
        {
            uint32_t g0 = bit1 ? h0 : h1, g1 = bit1 ? h2v : h3;
            uint32_t r0 = __shfl_xor_sync(0xffffffffu, g0, 2);
            uint32_t r1 = __shfl_xor_sync(0xffffffffu, g1, 2);
            h0 = hadd2u(bit1 ? h1 : h0, r0);
            h1 = hadd2u(bit1 ? h3 : h2v, r1);
        }
        // round 3 (xor 4)
        {
            uint32_t g0 = bit2 ? h0 : h1;
            uint32_t r0 = __shfl_xor_sync(0xffffffffu, g0, 4);
            h0 = hadd2u(bit2 ? h1 : h0, r0);
        }
        // rounds 4,5 (xor 8,16): plain accumulate
        h0 = hadd2u(h0, __shfl_xor_sync(0xffffffffu, h0, 8));
        h0 = hadd2u(h0, __shfl_xor_sync(0xffffffffu, h0, 16));

        // lanes 0-7: fold, stash, partial total
        float p = 0.f;
        if (lane < 8) {
            float2 f2 = __half22float2(u2h(h0));
            float v0 = f2.x * fo.x, v1 = f2.y * fo.y;
            colbuf[w * 8 + j8] = make_float2(v0, v1);
            p = v0 + v1;
        }
        p += __shfl_xor_sync(0xffffffffu, p, 1);
        p += __shfl_xor_sync(0xffffffffu, p, 2);
        p += __shfl_xor_sync(0xffffffffu, p, 4);
        if (lane == 0) redp[w] = p;

        BAR_SYNC(1, 640);                           // colbuf + redp ready

        if (tid < 160) {
            float4 q0 = *(const float4*)&redp[0];
            float4 q1 = *(const float4*)&redp[4];
            float4 q2 = *(const float4*)&redp[8];
            float4 q3 = *(const float4*)&redp[12];
            float4 q4 = *(const float4*)&redp[16];
            float tot = ((q0.x + q0.y) + (q0.z + q0.w)) + ((q1.x + q1.y) + (q1.z + q1.w))
                      + ((q2.x + q2.y) + (q2.z + q2.w)) + ((q3.x + q3.y) + (q3.z + q3.w))
                      + ((q4.x + q4.y) + (q4.z + q4.w));
            float si = __frcp_rn(tot);
            float2 f = colbuf[tid];
            float b0 = f.x * si * rsv.x, b1 = f.y * si * rsv.y;
            ah2[2 * tid]     = __floats2half2_rn(b0, b0);
            ah2[2 * tid + 1] = __floats2half2_rn(b1, b1);
            if (tid == 0) {                          // Kahan float log accumulation
                float y = logf(tot) - lcomp;
                float t2 = llf + y;
                lcomp = (t2 - llf) - y;
                llf = t2;
            }
        }
        BAR_SYNC(2, 640);                           // alpha ready
    }
    if (tid == 0) out[b] = (float)((double)llf - (double)NSTEP * LOG_SCALE_D);
}

// ---------------- launch ----------------
extern "C" void kernel_launch(void* const* d_in, const int* in_sizes, int n_in,
                              void* d_out, int out_size) {
    const float* inputs = (const float*)d_in[0];
    const float* initk  = (const float*)d_in[1];
    const float* transk = (const float*)d_in[2];
    const float* emisk  = (const float*)d_in[3];
    float* out = (float*)d_out;

    k_setup<<<1, 512>>>(initk, emisk);
    k_softA<<<NS, 320>>>(transk);
    k_gram<<<NB, 256>>>(inputs);
    k_gemm<<<dim3(5, 5, 4), 256>>>(0);
    k_gemm<<<dim3(5, 5, 64), 256>>>(1);
    k_quant<<<dim3(40, 69, 2), 256>>>();
    k_chain<<<NB, 640>>>(out);
}

// round 7
// speedup vs baseline: 1.3071x; 1.0228x over previous
#include <cuda_runtime.h>
#include <cuda_fp16.h>
#include <cuda_fp8.h>
#include <math.h>
#include <stdint.h>

#define NS 305
#define SP 320
#define SPSP (SP * SP)
#define NB 64
#define NT 4096
#define NTAU 1023            // 4-gram steps (t=1..4092)
#define NSTEP (NTAU + 2)     // + Q-step + A-step
#define LOG_SCALE_D 8.317766166719343   // log(4096)
#define DITH1 1.0471f        // dither factor for copy 1 (compensated exactly via g_rs)

// ---------------- device globals (zero-initialized) ----------------
__device__ float g_I[SP];
__device__ __align__(16) float g_BmT[4][SP];              // BmT[a][s] = Bm[s][a]
__device__ __align__(16) float g_A32[SPSP];
__device__ __align__(16) float g_Q32[4][SPSP];
__device__ __align__(16) float g_R32[64 * SPSP];          // fp32 R_{abc}
// e5m2, 2 dither copies, BLOCKED layout: byte for (row r, col c) at
// ((r>>5)*20 + (c>>4))*512 + (r&31)*16 + (c&15)
__device__ __align__(16) unsigned char g_S[2 * 69 * SPSP];
__device__ __align__(16) float g_rs[2 * 69 * SP];         // alpha row multiplier 4096/q per copy
__device__ unsigned char g_gram[NB * NTAU];
__device__ unsigned char g_o0[NB];
__device__ unsigned char g_tail[NB];

__device__ __forceinline__ float warpSum(float x) {
    #pragma unroll
    for (int o = 16; o; o >>= 1) x += __shfl_down_sync(0xffffffffu, x, o);
    return x;
}
__device__ __forceinline__ float warpMax(float x) {
    #pragma unroll
    for (int o = 16; o; o >>= 1) x = fmaxf(x, __shfl_down_sync(0xffffffffu, x, o));
    return x;
}
__device__ __forceinline__ float warpMaxAll(float x) {
    #pragma unroll
    for (int o = 16; o; o >>= 1) x = fmaxf(x, __shfl_xor_sync(0xffffffffu, x, o));
    return x;
}

__device__ __forceinline__ __half2 u2h(uint32_t u) { return *reinterpret_cast<__half2*>(&u); }
__device__ __forceinline__ uint32_t h2u(__half2 h) { return *reinterpret_cast<uint32_t*>(&h); }
__device__ __forceinline__ uint32_t hadd2u(uint32_t a, uint32_t b) {
    return h2u(__hadd2(u2h(a), u2h(b)));
}

#define BAR_SYNC(id, n)   asm volatile("bar.sync %0, %1;"   :: "n"(id), "n"(n) : "memory")

// ---------------- setup: I softmax + emission softmax ----------------
__global__ void k_setup(const float* __restrict__ initk, const float* __restrict__ emisk) {
    __shared__ float red[16];
    __shared__ float bval;
    int tid = threadIdx.x, wid = tid >> 5, lane = tid & 31;
    const int nw = 16;
    float v = (tid < NS) ? initk[tid] : -1e30f;
    float m = warpMax(v);
    if (lane == 0) red[wid] = m;
    __syncthreads();
    if (tid == 0) { float mm = -1e30f; for (int w = 0; w < nw; w++) mm = fmaxf(mm, red[w]); bval = mm; }
    __syncthreads();
    m = bval;
    float e = (tid < NS) ? expf(v - m) : 0.f;
    float s = warpSum(e);
    __syncthreads();
    if (lane == 0) red[wid] = s;
    __syncthreads();
    if (tid == 0) { float ss = 0.f; for (int w = 0; w < nw; w++) ss += red[w]; bval = ss; }
    __syncthreads();
    if (tid < NS) g_I[tid] = e / bval;

    if (tid < NS) {
        float x0 = emisk[tid * 4 + 0], x1 = emisk[tid * 4 + 1];
        float x2 = emisk[tid * 4 + 2], x3 = emisk[tid * 4 + 3];
        float mm = fmaxf(fmaxf(x0, x1), fmaxf(x2, x3));
        float e0 = expf(x0 - mm), e1 = expf(x1 - mm), e2 = expf(x2 - mm), e3 = expf(x3 - mm);
        float inv = 1.f / (e0 + e1 + e2 + e3);
        g_BmT[0][tid] = e0 * inv; g_BmT[1][tid] = e1 * inv;
        g_BmT[2][tid] = e2 * inv; g_BmT[3][tid] = e3 * inv;
    }
}

// ---------------- softmax rows of transition -> A32 ----------------
__global__ void k_softA(const float* __restrict__ trans) {
    __shared__ float red[10];
    __shared__ float bval;
    int r = blockIdx.x, tid = threadIdx.x;
    int wid = tid >> 5, lane = tid & 31;
    float v = (tid < NS) ? trans[r * NS + tid] : -1e30f;
    float m = warpMax(v);
    if (lane == 0) red[wid] = m;
    __syncthreads();
    if (tid == 0) { float mm = -1e30f; for (int w = 0; w < 10; w++) mm = fmaxf(mm, red[w]); bval = mm; }
    __syncthreads();
    m = bval;
    float e = (tid < NS) ? expf(v - m) : 0.f;
    float s = warpSum(e);
    __syncthreads();
    if (lane == 0) red[wid] = s;
    __syncthreads();
    if (tid == 0) { float ss = 0.f; for (int w = 0; w < 10; w++) ss += red[w]; bval = ss; }
    __syncthreads();
    if (tid < NS) g_A32[r * SP + tid] = e / bval;
}

// ---------------- observation -> gram indices ----------------
__global__ void k_gram(const float* __restrict__ inputs) {
    int b = blockIdx.x;
    const float* inb = inputs + (size_t)b * NT * 4;
    for (int tau = threadIdx.x; tau < NTAU; tau += blockDim.x) {
        int t0 = 1 + 4 * tau;
        unsigned g = 0;
        #pragma unroll
        for (int k = 0; k < 4; k++) {
            const float* p = inb + (size_t)(t0 + k) * 4;
            float fi = p[1] + 2.f * p[2] + 3.f * p[3];
            g = (g << 2) | (unsigned)(fi + 0.5f);
        }
        g_gram[b * NTAU + tau] = (unsigned char)g;
    }
    if (threadIdx.x == 0) {
        const float* p = inb;
        g_o0[b] = (unsigned char)(p[1] + 2.f * p[2] + 3.f * p[3] + 0.5f);
        unsigned tg = 0;
        #pragma unroll
        for (int k = 0; k < 3; k++) {
            const float* q = inb + (size_t)(4093 + k) * 4;
            tg = (tg << 2) | (unsigned)(q[1] + 2.f * q[2] + 3.f * q[3] + 0.5f);
        }
        g_tail[b] = (unsigned char)tg;
    }
}

// ---------------- fp32 GEMM with k-dim column scaling ----------------
__global__ void __launch_bounds__(256) k_gemm(int mode) {
    int z = blockIdx.z;
    const float *Lp, *Rp, *sc;
    float* outf;
    if (mode == 0) {
        Lp = g_A32; Rp = g_A32; sc = g_BmT[z]; outf = g_Q32[z];
    } else {
        int a = z >> 4, bb = (z >> 2) & 3, c = z & 3;
        Lp = g_Q32[a]; sc = g_BmT[bb]; Rp = g_Q32[c]; outf = g_R32 + (size_t)z * SPSP;
    }
    int m0 = blockIdx.y * 64, n0 = blockIdx.x * 64;
    __shared__ __align__(16) float Ls[16][64];
    __shared__ __align__(16) float Rs[16][64];
    int tid = threadIdx.x;
    int tx = tid & 15, ty = tid >> 4;
    int lrow = tid >> 2, lk = (tid & 3) * 4;
    int rk = tid >> 4, rn = (tid & 15) * 4;

    float acc[4][4] = {};
    for (int k0 = 0; k0 < SP; k0 += 16) {
        float4 lv = *(const float4*)&Lp[(size_t)(m0 + lrow) * SP + k0 + lk];
        Ls[lk + 0][lrow] = lv.x * sc[k0 + lk + 0];
        Ls[lk + 1][lrow] = lv.y * sc[k0 + lk + 1];
        Ls[lk + 2][lrow] = lv.z * sc[k0 + lk + 2];
        Ls[lk + 3][lrow] = lv.w * sc[k0 + lk + 3];
        *(float4*)&Rs[rk][rn] = *(const float4*)&Rp[(size_t)(k0 + rk) * SP + n0 + rn];
        __syncthreads();
        #pragma unroll
        for (int kk = 0; kk < 16; kk++) {
            float4 av = *(const float4*)&Ls[kk][ty * 4];
            float4 bv = *(const float4*)&Rs[kk][tx * 4];
            acc[0][0] = fmaf(av.x, bv.x, acc[0][0]); acc[0][1] = fmaf(av.x, bv.y, acc[0][1]);
            acc[0][2] = fmaf(av.x, bv.z, acc[0][2]); acc[0][3] = fmaf(av.x, bv.w, acc[0][3]);
            acc[1][0] = fmaf(av.y, bv.x, acc[1][0]); acc[1][1] = fmaf(av.y, bv.y, acc[1][1]);
            acc[1][2] = fmaf(av.y, bv.z, acc[1][2]); acc[1][3] = fmaf(av.y, bv.w, acc[1][3]);
            acc[2][0] = fmaf(av.z, bv.x, acc[2][0]); acc[2][1] = fmaf(av.z, bv.y, acc[2][1]);
            acc[2][2] = fmaf(av.z, bv.z, acc[2][2]); acc[2][3] = fmaf(av.z, bv.w, acc[2][3]);
            acc[3][0] = fmaf(av.w, bv.x, acc[3][0]); acc[3][1] = fmaf(av.w, bv.y, acc[3][1]);
            acc[3][2] = fmaf(av.w, bv.z, acc[3][2]); acc[3][3] = fmaf(av.w, bv.w, acc[3][3]);
        }
        __syncthreads();
    }
    #pragma unroll
    for (int i = 0; i < 4; i++)
        #pragma unroll
        for (int j = 0; j < 4; j++)
            outf[(size_t)(m0 + ty * 4 + i) * SP + (n0 + tx * 4 + j)] = acc[i][j];
}

// ---------------- quantize to e5m2, warp-per-row, blocked layout, 2 dithered copies ----------------
__global__ void k_quant() {
    int z = blockIdx.y, c = blockIdx.z;
    int warp = threadIdx.x >> 5, lane = threadIdx.x & 31;
    int r = blockIdx.x * 8 + warp;
    const float* src;
    if (z < 64) src = g_R32 + (size_t)z * SPSP;
    else if (z < 68) src = g_Q32[z - 64];
    else src = g_A32;
    const float* row = src + (size_t)r * SP;

    float vv[10];
    float mx = 0.f;
    #pragma unroll
    for (int i = 0; i < 10; i++) { vv[i] = row[lane + 32 * i]; mx = fmaxf(mx, vv[i]); }
    mx = warpMaxAll(mx);
    float q = (mx > 0.f) ? 384.f / mx : 1.f;
    if (c == 1) q *= DITH1;
    unsigned char* dst = g_S + ((size_t)c * 69 + z) * SPSP;
    int rk = r >> 5, rL = r & 31;
    #pragma unroll
    for (int i = 0; i < 10; i++) {
        int col = lane + 32 * i;
        dst[(((rk * 20 + (col >> 4)) * 32 + rL) << 4) + (col & 15)] =
            (unsigned char)__nv_cvt_float_to_fp8(vv[i] * q, __NV_SATFINITE, __NV_E5M2);
    }
    if (lane == 0) g_rs[(c * 69 + z) * SP + r] = 4096.f / q;
}

// ---------------- chain: single-barrier deferred-si pipeline ----------------
// 20 warps. Warp w owns cols [16w,16w+16); lane = row-class. One bar.sync/step.
// ah2 holds UNNORMALIZED alpha (missing si of its producing step); every warp
// applies si_prev (computed redundantly from redp at iter top) when finishing
// its own columns, then writes ONLY its own ah2 slice pre-barrier.
// Double-buffered ah2 + redp make this race-free: all cross-warp read/write
// pairs live in adjacent bar-intervals.
__global__ void __launch_bounds__(640, 1) k_chain(float* __restrict__ out) {
    int b = blockIdx.x, tid = threadIdx.x;
    __shared__ __half2 ah2[2][SP];
    __shared__ __align__(16) float redp[2][24];    // 96B rows keep float4 alignment
    __shared__ unsigned char sg[NTAU + 1];
    int lane = tid & 31, w = tid >> 5;

    for (int i = tid; i < NTAU; i += 640) sg[i] = g_gram[b * NTAU + i];
    unsigned tg = g_tail[b];
    int o0 = g_o0[b];
    if (tid < 24) { redp[0][tid] = 0.f; redp[1][tid] = (tid == 0) ? 1.f : 0.f; }
    __syncthreads();
    int z0 = sg[0] >> 2;

    // ---- prologue: alpha0 = normalize(I * Bm[:,o0]) -> ah2[0] (fully normalized) ----
    float llf = 0.f, lcomp = 0.f;
    {
        __shared__ float pr[20];
        __shared__ float psinv;
        __shared__ float af[SP];
        float v0p = (tid < SP) ? g_I[tid] * g_BmT[o0][tid] : 0.f;
        float wsum = warpSum(v0p);
        if (lane == 0) pr[w] = wsum;
        __syncthreads();
        if (tid == 0) {
            float x = 0.f;
            #pragma unroll
            for (int q = 0; q < 20; q++) x += pr[q];
            psinv = 1.f / x;
            pr[0] = x;
        }
        __syncthreads();
        llf = logf(pr[0]);
        if (tid < SP) af[tid] = v0p * psinv;
        __syncthreads();
        if (tid < 160) {
            float2 rsv = *(const float2*)&g_rs[z0 * SP + 2 * tid];   // step 0 = copy 0
            float a0 = af[2 * tid] * rsv.x, a1 = af[2 * tid + 1] * rsv.y;
            ah2[0][2 * tid]     = __floats2half2_rn(a0, a0);
            ah2[0][2 * tid + 1] = __floats2half2_rn(a1, a1);
        }
        __syncthreads();
    }

    // ---- preload matrix regs for step 0 (copy 0) ----
    uint4 mr[10];
    {
        const uint4* p = (const uint4*)(g_S + (size_t)z0 * SPSP) + tid;
        #pragma unroll
        for (int k = 0; k < 10; k++) mr[k] = __ldcg(p + k * 640);
    }

    int bit0 = lane & 1, bit1 = (lane >> 1) & 1, bit2 = (lane >> 2) & 1;
    int j8 = lane & 7;

    for (int step = 0; step < NSTEP; ++step) {
        int pb = step & 1, nb = 1 - pb;
        int d, zn;
        if (step < NTAU) d = sg[step] & 3;
        else if (step == NTAU) d = (tg >> 2) & 3;
        else d = tg & 3;
        if (step + 1 < NTAU) zn = sg[step + 1] >> 2;
        else if (step + 1 == NTAU) zn = 64 + ((tg >> 4) & 3);
        else zn = 68;
        int zoff = nb * 69 + zn;                   // dither copy alternates by step

        // si_prev from last step's totals (buffer nb holds s_{step-1}; init => 1 at step 0)
        float4 q0 = *(const float4*)&redp[nb][0];
        float4 q1 = *(const float4*)&redp[nb][4];
        float4 q2 = *(const float4*)&redp[nb][8];
        float4 q3 = *(const float4*)&redp[nb][12];
        float4 q4 = *(const float4*)&redp[nb][16];
        float tot = ((q0.x + q0.y) + (q0.z + q0.w)) + ((q1.x + q1.y) + (q1.z + q1.w))
                  + ((q2.x + q2.y) + (q2.z + q2.w)) + ((q3.x + q3.y) + (q3.z + q3.w))
                  + ((q4.x + q4.y) + (q4.z + q4.w));
        float si = __frcp_rn(tot);
        if (tid == 0) {                            // Kahan log of s_{step-1} (log(1)=0 at step 0)
            float y = logf(tot) - lcomp;
            float t2 = llf + y;
            lcomp = (t2 - llf) - y;
            llf = t2;
        }

        // prefetch fold (this step) + next row-scales (own 2 states)
        float2 fo  = *(const float2*)&g_BmT[d][16 * w + 2 * j8];
        float2 rsv = *(const float2*)&g_rs[(size_t)zoff * SP + 16 * w + 2 * j8];

        // ---- FMA phase: warp w, cols 16w..16w+15; lane rows lane+32k (reads ah2[pb]) ----
        __half2 a0 = __floats2half2_rn(0.f, 0.f);
        __half2 a1 = a0, a2 = a0, a3 = a0, a4 = a0, a5 = a0, a6 = a0, a7 = a0;
        #pragma unroll
        for (int k = 0; k < 10; k++) {
            __half2 av = ah2[pb][lane + 32 * k];
            a0 = __hfma2(av, u2h(__byte_perm(mr[k].x, 0, 0x1404)), a0);
            a1 = __hfma2(av, u2h(__byte_perm(mr[k].x, 0, 0x3424)), a1);
            a2 = __hfma2(av, u2h(__byte_perm(mr[k].y, 0, 0x1404)), a2);
            a3 = __hfma2(av, u2h(__byte_perm(mr[k].y, 0, 0x3424)), a3);
            a4 = __hfma2(av, u2h(__byte_perm(mr[k].z, 0, 0x1404)), a4);
            a5 = __hfma2(av, u2h(__byte_perm(mr[k].z, 0, 0x3424)), a5);
            a6 = __hfma2(av, u2h(__byte_perm(mr[k].w, 0, 0x1404)), a6);
            a7 = __hfma2(av, u2h(__byte_perm(mr[k].w, 0, 0x3424)), a7);
        }

        // ---- issue next step's matrix loads (mr regs now free) ----
        {
            const uint4* p = (const uint4*)(g_S + (size_t)zoff * SPSP) + tid;
            #pragma unroll
            for (int k = 0; k < 10; k++) mr[k] = __ldcg(p + k * 640);
        }

        // ---- in-warp reg-halving reduce: all lanes end with col pair j = lane&7 ----
        uint32_t h0 = h2u(a0), h1 = h2u(a1), h2v = h2u(a2), h3 = h2u(a3);
        uint32_t h4 = h2u(a4), h5 = h2u(a5), h6 = h2u(a6), h7 = h2u(a7);
        {
            uint32_t g0 = bit0 ? h0 : h1, g1 = bit0 ? h2v : h3;
            uint32_t g2 = bit0 ? h4 : h5, g3 = bit0 ? h6 : h7;
            uint32_t r0 = __shfl_xor_sync(0xffffffffu, g0, 1);
            uint32_t r1 = __shfl_xor_sync(0xffffffffu, g1, 1);
            uint32_t r2 = __shfl_xor_sync(0xffffffffu, g2, 1);
            uint32_t r3 = __shfl_xor_sync(0xffffffffu, g3, 1);
            h0 = hadd2u(bit0 ? h1 : h0, r0);
            h1 = hadd2u(bit0 ? h3 : h2v, r1);
            h2v = hadd2u(bit0 ? h5 : h4, r2);
            h3 = hadd2u(bit0 ? h7 : h6, r3);
        }
        {
            uint32_t g0 = bit1 ? h0 : h1, g1 = bit1 ? h2v : h3;
            uint32_t r0 = __shfl_xor_sync(0xffffffffu, g0, 2);
            uint32_t r1 = __shfl_xor_sync(0xffffffffu, g1, 2);
            h0 = hadd2u(bit1 ? h1 : h0, r0);
            h1 = hadd2u(bit1 ? h3 : h2v, r1);
        }
        {
            uint32_t g0 = bit2 ? h0 : h1;
            uint32_t r0 = __shfl_xor_sync(0xffffffffu, g0, 4);
            h0 = hadd2u(bit2 ? h1 : h0, r0);
        }
        h0 = hadd2u(h0, __shfl_xor_sync(0xffffffffu, h0, 8));
        h0 = hadd2u(h0, __shfl_xor_sync(0xffffffffu, h0, 16));

        // lanes 0-7: finish own 2 states — apply fold + si_prev, write ah2[nb] slice
        float p = 0.f;
        if (lane < 8) {
            float2 f2 = __half22float2(u2h(h0));
            float v0 = f2.x * fo.x * si, v1 = f2.y * fo.y * si;
            float b0 = v0 * rsv.x, b1 = v1 * rsv.y;     // next alpha, un-si'd (deferred)
            uint2 packed;
            packed.x = h2u(__floats2half2_rn(b0, b0));
            packed.y = h2u(__floats2half2_rn(b1, b1));
            *(uint2*)&ah2[nb][16 * w + 2 * j8] = packed;
            p = v0 + v1;                                 // contribution to s_step
        }
        p += __shfl_xor_sync(0xffffffffu, p, 1);
        p += __shfl_xor_sync(0xffffffffu, p, 2);
        p += __shfl_xor_sync(0xffffffffu, p, 4);
        if (lane == 0) redp[pb][w] = p;                  // publish s_step partial

        BAR_SYNC(1, 640);                                // the ONLY barrier per step
    }
    __syncthreads();
    if (tid == 0) {
        int fb = (NSTEP - 1) & 1;                        // buffer holding s_{NSTEP-1}
        float tot = 0.f;
        #pragma unroll
        for (int q = 0; q < 20; q++) tot += redp[fb][q];
        llf += logf(tot);
        out[b] = (float)((double)llf - (double)NSTEP * LOG_SCALE_D);
    }
}

// ---------------- launch ----------------
extern "C" void kernel_launch(void* const* d_in, const int* in_sizes, int n_in,
                              void* d_out, int out_size) {
    const float* inputs = (const float*)d_in[0];
    const float* initk  = (const float*)d_in[1];
    const float* transk = (const float*)d_in[2];
    const float* emisk  = (const float*)d_in[3];
    float* out = (float*)d_out;

    k_setup<<<1, 512>>>(initk, emisk);
    k_softA<<<NS, 320>>>(transk);
    k_gram<<<NB, 256>>>(inputs);
    k_gemm<<<dim3(5, 5, 4), 256>>>(0);
    k_gemm<<<dim3(5, 5, 64), 256>>>(1);
    k_quant<<<dim3(40, 69, 2), 256>>>();
    k_chain<<<NB, 640>>>(out);
}

// round 8
// speedup vs baseline: 1.3747x; 1.0517x over previous
#include <cuda_runtime.h>
#include <cuda_fp16.h>
#include <cuda_fp8.h>
#include <math.h>
#include <stdint.h>

#define NS 305
#define SP 320
#define SPSP (SP * SP)
#define NB 64
#define NT 4096
#define NTAU 1023            // 4-gram steps (t=1..4092)
#define NSTEP (NTAU + 2)     // + Q-step + A-step
#define LOG_SCALE_D 8.317766166719343   // log(4096)
#define DITH1 1.0471f        // dither factor for copy 1 (compensated exactly via g_rs)

// ---------------- device globals (zero-initialized) ----------------
__device__ float g_I[SP];
__device__ __align__(16) float g_BmT[4][SP];              // BmT[a][s] = Bm[s][a]
__device__ __align__(16) float g_A32[SPSP];
__device__ __align__(16) float g_Q32[4][SPSP];
__device__ __align__(16) float g_R32[64 * SPSP];          // fp32 R_{abc}
// e5m2, 2 dither copies, 8-col BLOCKED layout: byte for (row r, col c) at
// ((r>>5)*40 + (c>>3))*256 + (r&31)*8 + (c&7)
__device__ __align__(16) unsigned char g_S[2 * 69 * SPSP];
__device__ __align__(16) float g_rs[2 * 69 * SP];         // alpha row multiplier 4096/q per copy
__device__ unsigned char g_gram[NB * NTAU];
__device__ unsigned char g_o0[NB];
__device__ unsigned char g_tail[NB];

__device__ __forceinline__ float warpSum(float x) {
    #pragma unroll
    for (int o = 16; o; o >>= 1) x += __shfl_down_sync(0xffffffffu, x, o);
    return x;
}
__device__ __forceinline__ float warpMax(float x) {
    #pragma unroll
    for (int o = 16; o; o >>= 1) x = fmaxf(x, __shfl_down_sync(0xffffffffu, x, o));
    return x;
}
__device__ __forceinline__ float warpMaxAll(float x) {
    #pragma unroll
    for (int o = 16; o; o >>= 1) x = fmaxf(x, __shfl_xor_sync(0xffffffffu, x, o));
    return x;
}

__device__ __forceinline__ __half2 u2h(uint32_t u) { return *reinterpret_cast<__half2*>(&u); }
__device__ __forceinline__ uint32_t h2u(__half2 h) { return *reinterpret_cast<uint32_t*>(&h); }
__device__ __forceinline__ uint32_t hadd2u(uint32_t a, uint32_t b) {
    return h2u(__hadd2(u2h(a), u2h(b)));
}
__device__ __forceinline__ uint32_t s2u(const void* p) {
    uint32_t a;
    asm("{ .reg .u64 t; cvta.to.shared.u64 t, %1; cvt.u32.u64 %0, t; }" : "=r"(a) : "l"(p));
    return a;
}

// ---------------- setup: I softmax + emission softmax ----------------
__global__ void k_setup(const float* __restrict__ initk, const float* __restrict__ emisk) {
    __shared__ float red[16];
    __shared__ float bval;
    int tid = threadIdx.x, wid = tid >> 5, lane = tid & 31;
    const int nw = 16;
    float v = (tid < NS) ? initk[tid] : -1e30f;
    float m = warpMax(v);
    if (lane == 0) red[wid] = m;
    __syncthreads();
    if (tid == 0) { float mm = -1e30f; for (int w = 0; w < nw; w++) mm = fmaxf(mm, red[w]); bval = mm; }
    __syncthreads();
    m = bval;
    float e = (tid < NS) ? expf(v - m) : 0.f;
    float s = warpSum(e);
    __syncthreads();
    if (lane == 0) red[wid] = s;
    __syncthreads();
    if (tid == 0) { float ss = 0.f; for (int w = 0; w < nw; w++) ss += red[w]; bval = ss; }
    __syncthreads();
    if (tid < NS) g_I[tid] = e / bval;

    if (tid < NS) {
        float x0 = emisk[tid * 4 + 0], x1 = emisk[tid * 4 + 1];
        float x2 = emisk[tid * 4 + 2], x3 = emisk[tid * 4 + 3];
        float mm = fmaxf(fmaxf(x0, x1), fmaxf(x2, x3));
        float e0 = expf(x0 - mm), e1 = expf(x1 - mm), e2 = expf(x2 - mm), e3 = expf(x3 - mm);
        float inv = 1.f / (e0 + e1 + e2 + e3);
        g_BmT[0][tid] = e0 * inv; g_BmT[1][tid] = e1 * inv;
        g_BmT[2][tid] = e2 * inv; g_BmT[3][tid] = e3 * inv;
    }
}

// ---------------- softmax rows of transition -> A32 ----------------
__global__ void k_softA(const float* __restrict__ trans) {
    __shared__ float red[10];
    __shared__ float bval;
    int r = blockIdx.x, tid = threadIdx.x;
    int wid = tid >> 5, lane = tid & 31;
    float v = (tid < NS) ? trans[r * NS + tid] : -1e30f;
    float m = warpMax(v);
    if (lane == 0) red[wid] = m;
    __syncthreads();
    if (tid == 0) { float mm = -1e30f; for (int w = 0; w < 10; w++) mm = fmaxf(mm, red[w]); bval = mm; }
    __syncthreads();
    m = bval;
    float e = (tid < NS) ? expf(v - m) : 0.f;
    float s = warpSum(e);
    __syncthreads();
    if (lane == 0) red[wid] = s;
    __syncthreads();
    if (tid == 0) { float ss = 0.f; for (int w = 0; w < 10; w++) ss += red[w]; bval = ss; }
    __syncthreads();
    if (tid < NS) g_A32[r * SP + tid] = e / bval;
}

// ---------------- observation -> gram indices ----------------
__global__ void k_gram(const float* __restrict__ inputs) {
    int b = blockIdx.x;
    const float* inb = inputs + (size_t)b * NT * 4;
    for (int tau = threadIdx.x; tau < NTAU; tau += blockDim.x) {
        int t0 = 1 + 4 * tau;
        unsigned g = 0;
        #pragma unroll
        for (int k = 0; k < 4; k++) {
            const float* p = inb + (size_t)(t0 + k) * 4;
            float fi = p[1] + 2.f * p[2] + 3.f * p[3];
            g = (g << 2) | (unsigned)(fi + 0.5f);
        }
        g_gram[b * NTAU + tau] = (unsigned char)g;
    }
    if (threadIdx.x == 0) {
        const float* p = inb;
        g_o0[b] = (unsigned char)(p[1] + 2.f * p[2] + 3.f * p[3] + 0.5f);
        unsigned tg = 0;
        #pragma unroll
        for (int k = 0; k < 3; k++) {
            const float* q = inb + (size_t)(4093 + k) * 4;
            tg = (tg << 2) | (unsigned)(q[1] + 2.f * q[2] + 3.f * q[3] + 0.5f);
        }
        g_tail[b] = (unsigned char)tg;
    }
}

// ---------------- fp32 GEMM with k-dim column scaling ----------------
__global__ void __launch_bounds__(256) k_gemm(int mode) {
    int z = blockIdx.z;
    const float *Lp, *Rp, *sc;
    float* outf;
    if (mode == 0) {
        Lp = g_A32; Rp = g_A32; sc = g_BmT[z]; outf = g_Q32[z];
    } else {
        int a = z >> 4, bb = (z >> 2) & 3, c = z & 3;
        Lp = g_Q32[a]; sc = g_BmT[bb]; Rp = g_Q32[c]; outf = g_R32 + (size_t)z * SPSP;
    }
    int m0 = blockIdx.y * 64, n0 = blockIdx.x * 64;
    __shared__ __align__(16) float Ls[16][64];
    __shared__ __align__(16) float Rs[16][64];
    int tid = threadIdx.x;
    int tx = tid & 15, ty = tid >> 4;
    int lrow = tid >> 2, lk = (tid & 3) * 4;
    int rk = tid >> 4, rn = (tid & 15) * 4;

    float acc[4][4] = {};
    for (int k0 = 0; k0 < SP; k0 += 16) {
        float4 lv = *(const float4*)&Lp[(size_t)(m0 + lrow) * SP + k0 + lk];
        Ls[lk + 0][lrow] = lv.x * sc[k0 + lk + 0];
        Ls[lk + 1][lrow] = lv.y * sc[k0 + lk + 1];
        Ls[lk + 2][lrow] = lv.z * sc[k0 + lk + 2];
        Ls[lk + 3][lrow] = lv.w * sc[k0 + lk + 3];
        *(float4*)&Rs[rk][rn] = *(const float4*)&Rp[(size_t)(k0 + rk) * SP + n0 + rn];
        __syncthreads();
        #pragma unroll
        for (int kk = 0; kk < 16; kk++) {
            float4 av = *(const float4*)&Ls[kk][ty * 4];
            float4 bv = *(const float4*)&Rs[kk][tx * 4];
            acc[0][0] = fmaf(av.x, bv.x, acc[0][0]); acc[0][1] = fmaf(av.x, bv.y, acc[0][1]);
            acc[0][2] = fmaf(av.x, bv.z, acc[0][2]); acc[0][3] = fmaf(av.x, bv.w, acc[0][3]);
            acc[1][0] = fmaf(av.y, bv.x, acc[1][0]); acc[1][1] = fmaf(av.y, bv.y, acc[1][1]);
            acc[1][2] = fmaf(av.y, bv.z, acc[1][2]); acc[1][3] = fmaf(av.y, bv.w, acc[1][3]);
            acc[2][0] = fmaf(av.z, bv.x, acc[2][0]); acc[2][1] = fmaf(av.z, bv.y, acc[2][1]);
            acc[2][2] = fmaf(av.z, bv.z, acc[2][2]); acc[2][3] = fmaf(av.z, bv.w, acc[2][3]);
            acc[3][0] = fmaf(av.w, bv.x, acc[3][0]); acc[3][1] = fmaf(av.w, bv.y, acc[3][1]);
            acc[3][2] = fmaf(av.w, bv.z, acc[3][2]); acc[3][3] = fmaf(av.w, bv.w, acc[3][3]);
        }
        __syncthreads();
    }
    #pragma unroll
    for (int i = 0; i < 4; i++)
        #pragma unroll
        for (int j = 0; j < 4; j++)
            outf[(size_t)(m0 + ty * 4 + i) * SP + (n0 + tx * 4 + j)] = acc[i][j];
}

// ---------------- quantize to e5m2, warp-per-row, 8-col blocked layout, 2 dithered copies ----------------
__global__ void k_quant() {
    int z = blockIdx.y, c = blockIdx.z;
    int warp = threadIdx.x >> 5, lane = threadIdx.x & 31;
    int r = blockIdx.x * 8 + warp;
    const float* src;
    if (z < 64) src = g_R32 + (size_t)z * SPSP;
    else if (z < 68) src = g_Q32[z - 64];
    else src = g_A32;
    const float* row = src + (size_t)r * SP;

    float vv[10];
    float mx = 0.f;
    #pragma unroll
    for (int i = 0; i < 10; i++) { vv[i] = row[lane + 32 * i]; mx = fmaxf(mx, vv[i]); }
    mx = warpMaxAll(mx);
    float q = (mx > 0.f) ? 384.f / mx : 1.f;
    if (c == 1) q *= DITH1;
    unsigned char* dst = g_S + ((size_t)c * 69 + z) * SPSP;
    int rk = r >> 5, rL = r & 31;
    #pragma unroll
    for (int i = 0; i < 10; i++) {
        int col = lane + 32 * i;
        // 8-col blocked: ((rk*40 + (col>>3))*32 + rL)*8 + (col&7)
        dst[(((rk * 40 + (col >> 3)) * 32 + rL) << 3) + (col & 7)] =
            (unsigned char)__nv_cvt_float_to_fp8(vv[i] * q, __NV_SATFINITE, __NV_E5M2);
    }
    if (lane == 0) g_rs[(c * 69 + z) * SP + r] = 4096.f / q;
}

// ---------------- chain: 2-CTA cluster per batch, one mbarrier phase per step ----------------
// Cluster of 2 CTAs per batch; CTA rank owns cols [160*rank, 160*rank+160).
// 20 warps/CTA; warp w owns 8 cols (gcol base = 160*rank + 8w); lane = row-class (rows lane+32k).
// Per step: FMA (95 instr) -> in-warp shfl reduce -> lanes 0-3 write own 2-col alpha slice
// locally AND to peer (st.shared::cluster) -> remote mbar arrive (80/CTA) + local arrive (640)
// -> issue next mr loads -> try_wait parity(step&1). Arrive count = 640 + 80 = 720 per phase.
// Double-buffered ah2/redp: single phase per step bounds skew to one step => race-free.
__global__ void __launch_bounds__(640, 1) __cluster_dims__(2, 1, 1)
k_chain(float* __restrict__ out) {
    int tid = threadIdx.x;
    int b = blockIdx.x >> 1;
    uint32_t rank;
    asm("mov.u32 %0, %%cluster_ctarank;" : "=r"(rank));
    int peer = 1 - (int)rank;

    __shared__ __half2 ah2[2][SP];
    __shared__ __align__(16) float redp[2][48];    // slots 0..39 used (rank*20 + w)
    __shared__ unsigned char sg[NTAU + 1];
    __shared__ __align__(8) uint64_t mbar;
    __shared__ float pr[20];
    __shared__ float psinv;
    __shared__ float af[SP];

    int lane = tid & 31, w = tid >> 5;
    uint32_t mbarA = s2u(&mbar);

    for (int i = tid; i < NTAU; i += 640) sg[i] = g_gram[b * NTAU + i];
    unsigned tg = g_tail[b];
    int o0 = g_o0[b];
    if (tid < 48) { redp[0][tid] = 0.f; redp[1][tid] = (tid == 0) ? 1.f : 0.f; }
    if (tid == 0)
        asm volatile("mbarrier.init.shared.b64 [%0], %1;" :: "r"(mbarA), "r"(720) : "memory");
    __syncthreads();
    // peers must see initialized mbar before any remote arrive
    asm volatile("barrier.cluster.arrive.aligned;" ::: "memory");
    asm volatile("barrier.cluster.wait.aligned;" ::: "memory");

    int z0 = sg[0] >> 2;

    // ---- prologue: both CTAs build the FULL normalized alpha0 locally ----
    float llf = 0.f, lcomp = 0.f;
    {
        float v0p = (tid < SP) ? g_I[tid] * g_BmT[o0][tid] : 0.f;
        float wsum = warpSum(v0p);
        if (lane == 0) pr[w] = wsum;
        __syncthreads();
        if (tid == 0) {
            float x = 0.f;
            #pragma unroll
            for (int q = 0; q < 20; q++) x += pr[q];
            psinv = 1.f / x;
            pr[0] = x;
        }
        __syncthreads();
        llf = logf(pr[0]);
        if (tid < SP) af[tid] = v0p * psinv;
        __syncthreads();
        if (tid < 160) {
            float2 rsv = *(const float2*)&g_rs[z0 * SP + 2 * tid];   // step 0 = copy 0
            float a0 = af[2 * tid] * rsv.x, a1 = af[2 * tid + 1] * rsv.y;
            ah2[0][2 * tid]     = __floats2half2_rn(a0, a0);
            ah2[0][2 * tid + 1] = __floats2half2_rn(a1, a1);
        }
        __syncthreads();
    }

    int cb = (int)rank * 20 + w;                   // 8-col block index owned by this warp
    int gcol = (int)rank * 160 + 8 * w + 2 * (lane & 3);
    int slot = (int)rank * 20 + w;
    int bit0 = lane & 1, bit1 = (lane >> 1) & 1;

    // ---- preload mr for step 0 ----
    uint2 mr[10];
    {
        const uint2* base = (const uint2*)(g_S + (size_t)z0 * SPSP);
        #pragma unroll
        for (int k = 0; k < 10; k++) mr[k] = __ldcg(base + (k * 40 + cb) * 32 + lane);
    }

    for (int step = 0; step < NSTEP; ++step) {
        int pb = step & 1, nb = 1 - pb;
        int d, zn;
        if (step < NTAU) d = sg[step] & 3;
        else if (step == NTAU) d = (tg >> 2) & 3;
        else d = tg & 3;
        if (step + 1 < NTAU) zn = sg[step + 1] >> 2;
        else if (step + 1 == NTAU) zn = 64 + ((tg >> 4) & 3);
        else zn = 68;
        int zoff = nb * 69 + zn;

        // si_prev from last step's 40 global partials (fills mr-load latency window)
        float tot = 0.f;
        #pragma unroll
        for (int q = 0; q < 10; q++) {
            float4 t = *(const float4*)&redp[nb][4 * q];
            tot += (t.x + t.y) + (t.z + t.w);
        }
        float si = __frcp_rn(tot);
        if (rank == 0 && tid == 0) {               // Kahan log of s_{step-1}
            float y = logf(tot) - lcomp;
            float t2 = llf + y;
            lcomp = (t2 - llf) - y;
            llf = t2;
        }
        float2 fo  = *(const float2*)&g_BmT[d][gcol];
        float2 rsv = *(const float2*)&g_rs[(size_t)zoff * SP + gcol];

        // ---- FMA phase: 8 cols, rows lane+32k ----
        __half2 a0 = __floats2half2_rn(0.f, 0.f);
        __half2 a1 = a0, a2 = a0, a3 = a0;
        #pragma unroll
        for (int k = 0; k < 10; k++) {
            __half2 av = ah2[pb][lane + 32 * k];
            a0 = __hfma2(av, u2h(__byte_perm(mr[k].x, 0, 0x1404)), a0);
            a1 = __hfma2(av, u2h(__byte_perm(mr[k].x, 0, 0x3424)), a1);
            a2 = __hfma2(av, u2h(__byte_perm(mr[k].y, 0, 0x1404)), a2);
            a3 = __hfma2(av, u2h(__byte_perm(mr[k].y, 0, 0x3424)), a3);
        }

        // ---- in-warp reduce: lane ends holding col-pair (lane&3) total ----
        uint32_t h0 = h2u(a0), h1 = h2u(a1), h2v = h2u(a2), h3 = h2u(a3);
        {
            uint32_t g0 = bit0 ? h0 : h1, g1 = bit0 ? h2v : h3;
            uint32_t r0 = __shfl_xor_sync(0xffffffffu, g0, 1);
            uint32_t r1 = __shfl_xor_sync(0xffffffffu, g1, 1);
            h0 = hadd2u(bit0 ? h1 : h0, r0);
            h1 = hadd2u(bit0 ? h3 : h2v, r1);
        }
        {
            uint32_t g0 = bit1 ? h0 : h1;
            uint32_t r0 = __shfl_xor_sync(0xffffffffu, g0, 2);
            h0 = hadd2u(bit1 ? h1 : h0, r0);
        }
        h0 = hadd2u(h0, __shfl_xor_sync(0xffffffffu, h0, 4));
        h0 = hadd2u(h0, __shfl_xor_sync(0xffffffffu, h0, 8));
        h0 = hadd2u(h0, __shfl_xor_sync(0xffffffffu, h0, 16));

        // ---- lanes 0-3: finish own 2 cols, write local + remote alpha ----
        float p = 0.f;
        if (lane < 4) {
            float2 f2 = __half22float2(u2h(h0));
            float v0 = f2.x * fo.x * si, v1 = f2.y * fo.y * si;
            float b0 = v0 * rsv.x, b1 = v1 * rsv.y;   // next alpha, un-si'd (deferred)
            uint32_t pkx = h2u(__floats2half2_rn(b0, b0));
            uint32_t pky = h2u(__floats2half2_rn(b1, b1));
            uint2 pk = make_uint2(pkx, pky);
            *(uint2*)&ah2[nb][gcol] = pk;             // local
            uint64_t vv = ((uint64_t)pky << 32) | pkx;
            uint32_t la = s2u(&ah2[nb][gcol]);
            asm volatile(
                "{ .reg .b32 ra; mapa.shared::cluster.u32 ra, %0, %1;"
                "  st.shared::cluster.b64 [ra], %2; }"
                :: "r"(la), "r"(peer), "l"(vv) : "memory");
            p = v0 + v1;
        }
        p += __shfl_xor_sync(0xffffffffu, p, 1);
        p += __shfl_xor_sync(0xffffffffu, p, 2);
        if (lane == 0) {
            redp[pb][slot] = p;                       // local
            uint32_t la = s2u(&redp[pb][slot]);
            asm volatile(
                "{ .reg .b32 ra; mapa.shared::cluster.u32 ra, %0, %1;"
                "  st.shared::cluster.b32 [ra], %2; }"
                :: "r"(la), "r"(peer), "f"(p) : "memory");
        }
        // remote arrive (release, cluster) — orders the remote stores above
        if (lane < 4) {
            asm volatile(
                "{ .reg .b32 ra; mapa.shared::cluster.u32 ra, %0, %1;"
                "  mbarrier.arrive.shared::cluster.b64 _, [ra]; }"
                :: "r"(mbarA), "r"(peer) : "memory");
        }
        // local arrive (all 640)
        asm volatile("mbarrier.arrive.shared.b64 _, [%0];" :: "r"(mbarA) : "memory");

        // ---- issue next step's mr loads while the barrier settles ----
        {
            const uint2* base = (const uint2*)(g_S + (size_t)zoff * SPSP);
            #pragma unroll
            for (int k = 0; k < 10; k++) mr[k] = __ldcg(base + (k * 40 + cb) * 32 + lane);
        }

        // ---- wait for phase completion (720 arrives), cluster-acquire ----
        {
            uint32_t parity = (uint32_t)(step & 1);
            uint32_t done;
            asm volatile(
                "{ .reg .pred P;"
                "  mbarrier.try_wait.parity.acquire.cluster.shared::cta.b64 P, [%1], %2;"
                "  selp.b32 %0, 1, 0, P; }"
                : "=r"(done) : "r"(mbarA), "r"(parity) : "memory");
            if (!done) {
                asm volatile(
                    "{ .reg .pred P;"
                    "WL_%=:"
                    "  mbarrier.try_wait.parity.acquire.cluster.shared::cta.b64 P, [%0], %1, 0x989680;"
                    "  @P bra WD_%=;"
                    "  bra WL_%=;"
                    "WD_%=: }"
                    :: "r"(mbarA), "r"(parity) : "memory");
            }
        }
    }

    if (rank == 0 && tid == 0) {
        int fb = (NSTEP - 1) & 1;                    // buffer holding s_{NSTEP-1}
        float tot = 0.f;
        #pragma unroll
        for (int q = 0; q < 40; q++) tot += redp[fb][q];
        llf += logf(tot);
        out[b] = (float)((double)llf - (double)NSTEP * LOG_SCALE_D);
    }
}

// ---------------- launch ----------------
extern "C" void kernel_launch(void* const* d_in, const int* in_sizes, int n_in,
                              void* d_out, int out_size) {
    const float* inputs = (const float*)d_in[0];
    const float* initk  = (const float*)d_in[1];
    const float* transk = (const float*)d_in[2];
    const float* emisk  = (const float*)d_in[3];
    float* out = (float*)d_out;

    k_setup<<<1, 512>>>(initk, emisk);
    k_softA<<<NS, 320>>>(transk);
    k_gram<<<NB, 256>>>(inputs);
    k_gemm<<<dim3(5, 5, 4), 256>>>(0);
    k_gemm<<<dim3(5, 5, 64), 256>>>(1);
    k_quant<<<dim3(40, 69, 2), 256>>>();
    k_chain<<<NB * 2, 640>>>(out);
}